// round 1
// baseline (speedup 1.0000x reference)
#include <cuda_runtime.h>
#include <cuda_fp16.h>
#include <math.h>

#define BB 8
#define PP 16384
#define QQ 256
#define EE 128
#define QCAP 64
#define ECAP 32
#define NPIX (BB*PP)            // 131072
#define PCHUNKS_A 32
#define PIX_A (PP/PCHUNKS_A)    // 512
#define PCB 8                   // pass-B P-chunks
#define PIX_B (PP/PCB)          // 2048
#define ESTRIDE 65              // padded smem stride (bank-conflict-free)

// ---------------- scratch (static device globals; no allocation) -------------
__device__ int           g_mask_dtype;            // 0=bool/u8, 1=f32, 2=i32
__device__ unsigned char g_qidx[NPIX*QCAP];       // 8 MB
__device__ __half        g_a1  [NPIX*QCAP];       // 16 MB  (-x on masked entries)
__device__ __half        g_pp  [NPIX*QCAP];       // 16 MB  (softmax prob)
__device__ int           g_qcnt[NPIX];
__device__ unsigned char g_eidx[NPIX*ECAP];       // 4 MB
__device__ __half        g_ev  [NPIX*ECAP];       // 8 MB   (segmap value)
__device__ int           g_ecnt[NPIX];
__device__ float g_negsum[BB*QQ];
__device__ float g_psum  [BB*QQ];
__device__ float g_segsum[BB*EE];
__device__ float g_nnz   [BB];
__device__ float g_part1[PCB*BB*2*QQ*64];         // 8 MB
__device__ float g_part2[PCB*BB*2*QQ*64];         // 8 MB

// ---------------- dtype detection for mask_mask ------------------------------
__global__ void k_detect(const unsigned int* __restrict__ w, int nwords) {
    __shared__ int sF, sB;
    if (threadIdx.x == 0) { sF = 0; sB = 0; }
    __syncthreads();
    int f = 0, bl = 0;
    for (int i = threadIdx.x; i < nwords; i += blockDim.x) {
        unsigned v = w[i];
        if (v == 0x3F800000u) f = 1;
        else if (v & 0xFFFFFF00u) bl = 1;
    }
    if (f)  atomicOr(&sF, 1);
    if (bl) atomicOr(&sB, 1);
    __syncthreads();
    if (threadIdx.x == 0) g_mask_dtype = sF ? 1 : (sB ? 0 : 2);
}

__global__ void k_init() {
    for (int k = threadIdx.x; k < BB*QQ; k += 256) { g_negsum[k] = 0.f; g_psum[k] = 0.f; }
    for (int k = threadIdx.x; k < BB*EE; k += 256) g_segsum[k] = 0.f;
    if (threadIdx.x < BB) g_nnz[threadIdx.x] = 0.f;
}

// ---------------- pass A: elementwise + softmax + compaction -----------------
__global__ void __launch_bounds__(256) k_passA(
    const float* __restrict__ mlv, const void* __restrict__ maskp,
    const float* __restrict__ seg)
{
    const int b = blockIdx.y, pc = blockIdx.x;
    const int lane = threadIdx.x & 31, w = threadIdx.x >> 5;
    __shared__ float negsh[QQ], psh[QQ], segsh[EE];
    __shared__ int nnzsh;
    for (int k = threadIdx.x; k < QQ; k += 256) { negsh[k] = 0.f; psh[k] = 0.f; }
    for (int k = threadIdx.x; k < EE; k += 256) segsh[k] = 0.f;
    if (threadIdx.x == 0) nnzsh = 0;
    __syncthreads();

    const int mdt = g_mask_dtype;
    const unsigned lmask = (1u << lane) - 1u;

    for (int pi = w; pi < PIX_A; pi += 8) {
        const int p = pc * PIX_A + pi;
        const size_t pix  = (size_t)b * PP + p;
        const size_t rowQ = pix * QQ;
        const int q0 = lane * 8;

        // --- load 8 logits (vectorized) ---
        const float4* xr = reinterpret_cast<const float4*>(mlv + rowQ);
        float4 xa = xr[lane*2], xb = xr[lane*2 + 1];
        float x[8] = {xa.x, xa.y, xa.z, xa.w, xb.x, xb.y, xb.z, xb.w};

        // --- load 8 mask flags per detected dtype ---
        unsigned mbits = 0;
        if (mdt == 0) {
            const unsigned char* mv = (const unsigned char*)maskp + rowQ;
            uint2 u = *reinterpret_cast<const uint2*>(mv + (size_t)lane * 8);
            #pragma unroll
            for (int j = 0; j < 4; j++) {
                if ((u.x >> (8*j)) & 0xffu) mbits |= 1u << j;
                if ((u.y >> (8*j)) & 0xffu) mbits |= 1u << (4 + j);
            }
        } else if (mdt == 1) {
            const float4* mv = reinterpret_cast<const float4*>((const float*)maskp + rowQ);
            float4 a = mv[lane*2], c = mv[lane*2 + 1];
            float mm[8] = {a.x, a.y, a.z, a.w, c.x, c.y, c.z, c.w};
            #pragma unroll
            for (int j = 0; j < 8; j++) if (mm[j] != 0.f) mbits |= 1u << j;
        } else {
            const int4* mv = reinterpret_cast<const int4*>((const int*)maskp + rowQ);
            int4 a = mv[lane*2], c = mv[lane*2 + 1];
            int mm[8] = {a.x, a.y, a.z, a.w, c.x, c.y, c.z, c.w};
            #pragma unroll
            for (int j = 0; j < 8; j++) if (mm[j] != 0) mbits |= 1u << j;
        }

        // --- masked row max over Q ---
        float mx = -1e30f;
        #pragma unroll
        for (int j = 0; j < 8; j++) if ((mbits >> j) & 1) mx = fmaxf(mx, x[j]);
        #pragma unroll
        for (int o = 16; o; o >>= 1) mx = fmaxf(mx, __shfl_xor_sync(0xffffffffu, mx, o));

        // --- exp + sum ---
        float ez[8]; float s = 0.f;
        #pragma unroll
        for (int j = 0; j < 8; j++) {
            ez[j] = ((mbits >> j) & 1) ? __expf(x[j] - mx) : 0.f;
            s += ez[j];
        }
        #pragma unroll
        for (int o = 16; o; o >>= 1) s += __shfl_xor_sync(0xffffffffu, s, o);
        const float inv = (s > 0.f) ? (1.f / s) : 0.f;   // s >= 1 if any masked

        // --- compaction + vector accumulators ---
        unsigned char* qp  = g_qidx + pix * QCAP;
        __half*        ap  = g_a1   + pix * QCAP;
        __half*        ppp = g_pp   + pix * QCAP;
        int base = 0;
        #pragma unroll
        for (int j = 0; j < 8; j++) {
            bool mj = (mbits >> j) & 1;
            unsigned bal = __ballot_sync(0xffffffffu, mj);
            if (mj) {
                int pos = base + __popc(bal & lmask);
                if (pos < QCAP) {
                    qp[pos]  = (unsigned char)(q0 + j);
                    ap[pos]  = __float2half(-x[j]);
                    ppp[pos] = __float2half(ez[j] * inv);
                }
                float xx  = x[j];
                float spx = fmaxf(xx, 0.f) + log1pf(__expf(-fabsf(xx)));  // softplus(x)
                atomicAdd(&negsh[q0 + j], spx);
                atomicAdd(&psh[q0 + j], ez[j] * inv);
            }
            base += __popc(bal);
        }
        if (lane == 0) g_qcnt[pix] = min(base, QCAP);

        // --- segmap row (E=128, 4 per lane) ---
        const float4 sv4 = reinterpret_cast<const float4*>(seg + pix * EE)[lane];
        float sv[4] = {sv4.x, sv4.y, sv4.z, sv4.w};
        unsigned char* ep  = g_eidx + pix * ECAP;
        __half*        evp = g_ev   + pix * ECAP;
        int ebase = 0;
        #pragma unroll
        for (int j = 0; j < 4; j++) {
            bool t = sv[j] > 0.f;
            unsigned bal = __ballot_sync(0xffffffffu, t);
            if (t) {
                int pos = ebase + __popc(bal & lmask);
                if (pos < ECAP) {
                    ep[pos]  = (unsigned char)(lane * 4 + j);
                    evp[pos] = __float2half(sv[j]);
                }
                atomicAdd(&segsh[lane * 4 + j], sv[j]);
            }
            ebase += __popc(bal);
        }
        if (lane == 0) {
            g_ecnt[pix] = min(ebase, ECAP);
            atomicAdd(&nnzsh, ebase);
        }
    }

    __syncthreads();
    const int t = threadIdx.x;
    if (t < QQ) {
        atomicAdd(&g_negsum[b*QQ + t], negsh[t]);
        atomicAdd(&g_psum  [b*QQ + t], psh[t]);
    }
    if (t < EE) atomicAdd(&g_segsum[b*EE + t], segsh[t]);
    if (t == 0) atomicAdd(&g_nnz[b], (float)nnzsh);
}

// ---------------- pass B: sparse outer-product accumulation ------------------
__global__ void __launch_bounds__(256) k_passB() {
    extern __shared__ float sh[];
    float* M1h = sh;                     // [QQ][ESTRIDE]
    float* M2h = sh + QQ * ESTRIDE;
    const int pc = blockIdx.x, b = blockIdx.y, eh = blockIdx.z;
    const int lane = threadIdx.x & 31, w = threadIdx.x >> 5;

    for (int k = threadIdx.x; k < 2 * QQ * ESTRIDE; k += 256) sh[k] = 0.f;
    __syncthreads();

    for (int pi = w; pi < PIX_B; pi += 8) {
        const size_t pix = (size_t)b * PP + (size_t)pc * PIX_B + pi;
        const int nq = g_qcnt[pix];
        const int ne = g_ecnt[pix];
        if (nq == 0 || ne == 0) continue;

        int nep2 = 1; while (nep2 < ne) nep2 <<= 1;     // <= 32
        const int lg = __popc(nep2 - 1);
        const int j  = lane & (nep2 - 1);

        bool keep = false; int el = 0; float svj = 0.f;
        if (j < ne) {
            int ej = g_eidx[pix * ECAP + j];
            if ((ej >> 6) == eh) {
                keep = true; el = ej & 63;
                svj = __half2float(g_ev[pix * ECAP + j]);
            }
        }
        if (!__any_sync(0xffffffffu, keep)) continue;

        for (int i = lane >> lg; i < nq; i += (32 >> lg)) {
            if (keep) {
                int   q  = g_qidx[pix * QCAP + i];
                float a1 = __half2float(g_a1[pix * QCAP + i]);
                float pp = __half2float(g_pp[pix * QCAP + i]);
                atomicAdd(&M1h[q * ESTRIDE + el], a1);
                atomicAdd(&M2h[q * ESTRIDE + el], pp * svj);
            }
        }
    }
    __syncthreads();

    const size_t base = (size_t)(((pc * BB + b) * 2 + eh)) * QQ * 64;
    for (int k = threadIdx.x; k < QQ * 64; k += 256) {
        g_part1[base + k] = M1h[(k >> 6) * ESTRIDE + (k & 63)];
        g_part2[base + k] = M2h[(k >> 6) * ESTRIDE + (k & 63)];
    }
}

// ---------------- final: reduce partials + cheap costs -----------------------
__global__ void __launch_bounds__(256) k_final(
    const float* __restrict__ logits, const float* __restrict__ ppos,
    const float* __restrict__ chol,   const float* __restrict__ tpos,
    const float* __restrict__ imsz,   float* __restrict__ out)
{
    const int idx = blockIdx.x * 256 + threadIdx.x;
    if (idx >= BB * QQ * EE) return;
    const int e = idx & (EE - 1);
    const int q = (idx >> 7) & (QQ - 1);
    const int b = idx >> 15;
    const int eh = e >> 6, el = e & 63;

    float M1 = 0.f, M2 = 0.f;
    #pragma unroll
    for (int pcc = 0; pcc < PCB; pcc++) {
        size_t off = ((size_t)((pcc * BB + b) * 2 + eh) * QQ + q) * 64 + el;
        M1 += g_part1[off];
        M2 += g_part2[off];
    }

    const float lgt = logits[b * QQ + q];
    const float cls = fmaxf(-lgt, 0.f) + log1pf(__expf(-fabsf(lgt)));   // softplus(-logit)
    const float nnz = fmaxf(g_nnz[b], 1.f);
    const float maskc = (M1 + g_negsum[b * QQ + q]) / nnz;
    const float dice  = 1.f - (2.f * M2 + 1.f) / (g_psum[b * QQ + q] + g_segsum[b * EE + e] + 1.f);

    const float px = ppos[(b * QQ + q) * 2 + 0], py = ppos[(b * QQ + q) * 2 + 1];
    const float tx = tpos[(b * EE + e) * 2 + 0], ty = tpos[(b * EE + e) * 2 + 1];
    const float d0 = px - tx, d1 = py - ty;
    const float a0 = fabsf(d0), a1 = fabsf(d1);
    const float h0 = (a0 < 1.f) ? 0.5f * d0 * d0 : a0 - 0.5f;
    const float h1 = (a1 < 1.f) ? 0.5f * d1 * d1 : a1 - 0.5f;
    const float hub = 0.5f * (h0 + h1);

    const float sx = imsz[b * 2 + 0], sy = imsz[b * 2 + 1];
    const float L00 = chol[(b * QQ + q) * 4 + 0];
    const float L10 = chol[(b * QQ + q) * 4 + 2];
    const float L11 = chol[(b * QQ + q) * 4 + 3];
    const float D0 = (tx - px) * sx, D1 = (ty - py) * sy;
    const float z0 = D0 / L00;
    const float z1 = (D1 - L10 * z0) / L11;
    const float nll = 0.5f * (z0 * z0 + z1 * z1) + 1.837877066409345f + logf(L00) + logf(L11);
    const float lik = 1.f - __expf(-nll);

    out[idx] = 2.f * cls + 5.f * maskc + 5.f * dice + hub + 0.5f * nll + 0.5f * lik;
}

// ---------------- launch -----------------------------------------------------
extern "C" void kernel_launch(void* const* d_in, const int* in_sizes, int n_in,
                              void* d_out, int out_size)
{
    const float* pred_logits = (const float*)d_in[0];
    const float* mlv         = (const float*)d_in[1];
    const void*  mm          = d_in[2];
    const float* seg         = (const float*)d_in[3];
    const float* ppos        = (const float*)d_in[4];
    const float* chol        = (const float*)d_in[5];
    const float* tpos        = (const float*)d_in[6];
    const float* imsz        = (const float*)d_in[7];
    float* out = (float*)d_out;

    // Safe scan size: mask buffer is >= n_elems bytes; n_elems/4 words always valid.
    int nwords = in_sizes[2] / 4;
    if (nwords > 262144) nwords = 262144;

    k_detect<<<1, 256>>>((const unsigned int*)mm, nwords);
    k_init<<<1, 256>>>();

    dim3 gA(PCHUNKS_A, BB);
    k_passA<<<gA, 256>>>(mlv, mm, seg);

    cudaFuncSetAttribute(k_passB, cudaFuncAttributeMaxDynamicSharedMemorySize,
                         2 * QQ * ESTRIDE * 4);
    dim3 gB(PCB, BB, 2);
    k_passB<<<gB, 256, 2 * QQ * ESTRIDE * 4>>>();

    k_final<<<(BB * QQ * EE + 255) / 256, 256>>>(pred_logits, ppos, chol, tpos, imsz, out);
}

// round 2
// speedup vs baseline: 2.7204x; 2.7204x over previous
#include <cuda_runtime.h>
#include <cuda_fp16.h>
#include <math.h>

#define BB 8
#define PP 16384
#define QQ 256
#define EE 128
#define QCAP 64
#define ECAP 32
#define NPIX (BB*PP)            // 131072
#define PCHUNKS_A 64
#define PIX_A (PP/PCHUNKS_A)    // 256
#define PCB 16                  // pass-B P-chunks
#define PIX_B (PP/PCB)          // 1024
#define EQ 4                    // e quarters
#define EQW 32                  // e quarter width
#define QS 257                  // padded q stride in passB smem

// ---------------- scratch (static device globals; no allocation) -------------
__device__ int          g_mask_dtype;          // 0=bool/u8, 1=f32, 2=i32
__device__ uint2        g_qe[NPIX*QCAP];       // packed: q | half(-x)<<16 ; half(p)
__device__ unsigned int g_ee[NPIX*ECAP];       // packed: e | half(sv)<<16
__device__ unsigned int g_cnt[NPIX];           // nq | ne<<16
__device__ float g_negsum[BB*QQ];
__device__ float g_psum  [BB*QQ];
__device__ float g_segsum[BB*EE];
__device__ float g_nnz   [BB];
__device__ float g_M1[BB*QQ*EE];               // 1 MB
__device__ float g_M2[BB*QQ*EE];               // 1 MB

// ---------------- dtype detection for mask_mask ------------------------------
__global__ void k_detect(const unsigned int* __restrict__ w, int nwords) {
    __shared__ int sF, sB;
    if (threadIdx.x == 0) { sF = 0; sB = 0; }
    __syncthreads();
    int f = 0, bl = 0;
    for (int i = threadIdx.x; i < nwords; i += blockDim.x) {
        unsigned v = __ldg(w + i);
        if (v == 0x3F800000u) f = 1;
        else if (v & 0xFFFFFF00u) bl = 1;
    }
    if (f)  atomicOr(&sF, 1);
    if (bl) atomicOr(&sB, 1);
    __syncthreads();
    if (threadIdx.x == 0) g_mask_dtype = sF ? 1 : (sB ? 0 : 2);
}

// ---------------- zero accumulators ------------------------------------------
__global__ void k_init() {
    const int t = blockIdx.x * blockDim.x + threadIdx.x;           // 32768 threads
    float4 z = make_float4(0.f, 0.f, 0.f, 0.f);
    float4* m1 = reinterpret_cast<float4*>(g_M1);
    float4* m2 = reinterpret_cast<float4*>(g_M2);
    #pragma unroll
    for (int r = 0; r < 2; r++) { m1[t + r*32768] = z; m2[t + r*32768] = z; }
    if (t < BB*QQ) { g_negsum[t] = 0.f; g_psum[t] = 0.f; }
    if (t < BB*EE) g_segsum[t] = 0.f;
    if (t < BB) g_nnz[t] = 0.f;
}

// ---------------- pass A: elementwise + softmax + compaction -----------------
__global__ void __launch_bounds__(256) k_passA(
    const float* __restrict__ mlv, const void* __restrict__ maskp,
    const float* __restrict__ seg)
{
    const int b = blockIdx.y, pc = blockIdx.x;
    const int lane = threadIdx.x & 31, w = threadIdx.x >> 5;
    const int mdt = g_mask_dtype;
    const unsigned lmask = (1u << lane) - 1u;
    const int q0 = lane * 8;

    float negacc[8], psacc[8], segacc[4];
    #pragma unroll
    for (int j = 0; j < 8; j++) { negacc[j] = 0.f; psacc[j] = 0.f; }
    #pragma unroll
    for (int j = 0; j < 4; j++) segacc[j] = 0.f;
    float nnzacc = 0.f;

    for (int pi = w; pi < PIX_A; pi += 8) {
        const size_t pix  = (size_t)b * PP + pc * PIX_A + pi;
        const size_t rowQ = pix * QQ;

        // --- 8 logits (vectorized) ---
        const float4* xr = reinterpret_cast<const float4*>(mlv + rowQ);
        float4 xa = xr[lane*2], xb = xr[lane*2 + 1];
        float x[8] = {xa.x, xa.y, xa.z, xa.w, xb.x, xb.y, xb.z, xb.w};

        // --- 8 mask flags per detected dtype ---
        unsigned mbits = 0;
        if (mdt == 0) {
            const unsigned char* mv = (const unsigned char*)maskp + rowQ;
            uint2 u = *reinterpret_cast<const uint2*>(mv + (size_t)lane * 8);
            #pragma unroll
            for (int j = 0; j < 4; j++) {
                if ((u.x >> (8*j)) & 0xffu) mbits |= 1u << j;
                if ((u.y >> (8*j)) & 0xffu) mbits |= 1u << (4 + j);
            }
        } else if (mdt == 1) {
            const float4* mv = reinterpret_cast<const float4*>((const float*)maskp + rowQ);
            float4 a = mv[lane*2], c = mv[lane*2 + 1];
            float mm[8] = {a.x, a.y, a.z, a.w, c.x, c.y, c.z, c.w};
            #pragma unroll
            for (int j = 0; j < 8; j++) if (mm[j] != 0.f) mbits |= 1u << j;
        } else {
            const int4* mv = reinterpret_cast<const int4*>((const int*)maskp + rowQ);
            int4 a = mv[lane*2], c = mv[lane*2 + 1];
            int mm[8] = {a.x, a.y, a.z, a.w, c.x, c.y, c.z, c.w};
            #pragma unroll
            for (int j = 0; j < 8; j++) if (mm[j] != 0) mbits |= 1u << j;
        }

        // --- masked row max over Q ---
        float mx = -1e30f;
        #pragma unroll
        for (int j = 0; j < 8; j++) if ((mbits >> j) & 1) mx = fmaxf(mx, x[j]);
        #pragma unroll
        for (int o = 16; o; o >>= 1) mx = fmaxf(mx, __shfl_xor_sync(0xffffffffu, mx, o));

        // --- exp + sum ---
        float ez[8]; float s = 0.f;
        #pragma unroll
        for (int j = 0; j < 8; j++) {
            ez[j] = ((mbits >> j) & 1) ? __expf(x[j] - mx) : 0.f;
            s += ez[j];
        }
        #pragma unroll
        for (int o = 16; o; o >>= 1) s += __shfl_xor_sync(0xffffffffu, s, o);
        const float inv = (s > 0.f) ? (1.f / s) : 0.f;

        // --- compaction (packed uint2) + register accumulators ---
        uint2* qp = g_qe + pix * QCAP;
        int base = 0;
        #pragma unroll
        for (int j = 0; j < 8; j++) {
            bool mj = (mbits >> j) & 1;
            unsigned bal = __ballot_sync(0xffffffffu, mj);
            if (mj) {
                int pos = base + __popc(bal & lmask);
                if (pos < QCAP) {
                    unsigned a1h = __half_as_ushort(__float2half(-x[j]));
                    unsigned pph = __half_as_ushort(__float2half(ez[j] * inv));
                    qp[pos] = make_uint2((unsigned)(q0 + j) | (a1h << 16), pph);
                }
                float xx = x[j];
                negacc[j] += fmaxf(xx, 0.f) + log1pf(__expf(-fabsf(xx)));  // softplus(x)
                psacc[j]  += ez[j] * inv;
            }
            base += __popc(bal);
        }

        // --- segmap row (E=128, 4 per lane) ---
        const float4 sv4 = reinterpret_cast<const float4*>(seg + pix * EE)[lane];
        float sv[4] = {sv4.x, sv4.y, sv4.z, sv4.w};
        unsigned* ep = g_ee + pix * ECAP;
        int ebase = 0;
        #pragma unroll
        for (int j = 0; j < 4; j++) {
            bool t = sv[j] > 0.f;
            unsigned bal = __ballot_sync(0xffffffffu, t);
            if (t) {
                int pos = ebase + __popc(bal & lmask);
                if (pos < ECAP) {
                    unsigned svh = __half_as_ushort(__float2half(sv[j]));
                    ep[pos] = (unsigned)(lane * 4 + j) | (svh << 16);
                }
                segacc[j] += sv[j];
            }
            ebase += __popc(bal);
        }
        nnzacc += (float)ebase;
        if (lane == 0)
            g_cnt[pix] = (unsigned)min(base, QCAP) | ((unsigned)min(ebase, ECAP) << 16);
    }

    // --- flush register accumulators (global RED, no return) ---
    #pragma unroll
    for (int j = 0; j < 8; j++) {
        if (negacc[j] != 0.f) atomicAdd(&g_negsum[b*QQ + q0 + j], negacc[j]);
        if (psacc[j]  != 0.f) atomicAdd(&g_psum  [b*QQ + q0 + j], psacc[j]);
    }
    #pragma unroll
    for (int j = 0; j < 4; j++)
        if (segacc[j] != 0.f) atomicAdd(&g_segsum[b*EE + lane*4 + j], segacc[j]);
    if (lane == 0 && nnzacc != 0.f) atomicAdd(&g_nnz[b], nnzacc);
}

// ---------------- pass B: sparse outer-product accumulation ------------------
__global__ void __launch_bounds__(256) k_passB() {
    extern __shared__ float sh[];
    float* M1h = sh;                 // [EQW][QS]
    float* M2h = sh + EQW * QS;
    const int eq = blockIdx.x, b = blockIdx.y, pc = blockIdx.z;
    const int e0 = eq * EQW;
    const int lane = threadIdx.x & 31, w = threadIdx.x >> 5;

    for (int k = threadIdx.x; k < 2 * EQW * QS; k += 256) sh[k] = 0.f;
    __syncthreads();

    for (int pi = w; pi < PIX_B; pi += 8) {
        const size_t pix = (size_t)b * PP + (size_t)pc * PIX_B + pi;
        const unsigned cnt = g_cnt[pix];
        const int nq = cnt & 0xffff;
        const int ne = cnt >> 16;
        if (nq == 0 || ne == 0) continue;

        // e filter: lane j holds entry j
        int elj = 0; float svj = 0.f; bool ve = false;
        if (lane < ne) {
            unsigned v = g_ee[pix * ECAP + lane];
            int e = v & 0xff;
            if ((e >> 5) == eq) {
                ve = true; elj = e & 31;
                svj = __half2float(__ushort_as_half((unsigned short)(v >> 16)));
            }
        }
        unsigned eb = __ballot_sync(0xffffffffu, ve);
        if (!eb) continue;

        const uint2* qp = g_qe + pix * QCAP;
        for (int r = 0; r < nq; r += 32) {
            const int i = r + lane;
            const bool hq = i < nq;
            int q = 0; float a1 = 0.f, pp = 0.f;
            if (hq) {
                uint2 ent = qp[i];
                q  = ent.x & 0xff;
                a1 = __half2float(__ushort_as_half((unsigned short)(ent.x >> 16)));
                pp = __half2float(__ushort_as_half((unsigned short)(ent.y & 0xffff)));
            }
            unsigned eb2 = eb;
            while (eb2) {
                int jb = __ffs(eb2) - 1; eb2 &= eb2 - 1;
                int   el = __shfl_sync(0xffffffffu, elj, jb);
                float svv = __shfl_sync(0xffffffffu, svj, jb);
                if (hq) {
                    atomicAdd(&M1h[el * QS + q], a1);
                    atomicAdd(&M2h[el * QS + q], pp * svv);
                }
            }
        }
    }
    __syncthreads();

    // flush tile -> global RED (coalesced)
    for (int k = threadIdx.x; k < QQ * EQW; k += 256) {
        const int q = k >> 5, el = k & 31;
        float v1 = M1h[el * QS + q];
        float v2 = M2h[el * QS + q];
        const size_t off = ((size_t)(b * QQ + q)) * EE + e0 + el;
        if (v1 != 0.f) atomicAdd(&g_M1[off], v1);
        if (v2 != 0.f) atomicAdd(&g_M2[off], v2);
    }
}

// ---------------- final: cheap per-(b,q,e) costs -----------------------------
__global__ void __launch_bounds__(256) k_final(
    const float* __restrict__ logits, const float* __restrict__ ppos,
    const float* __restrict__ chol,   const float* __restrict__ tpos,
    const float* __restrict__ imsz,   float* __restrict__ out)
{
    const int idx = blockIdx.x * 256 + threadIdx.x;
    if (idx >= BB * QQ * EE) return;
    const int e = idx & (EE - 1);
    const int q = (idx >> 7) & (QQ - 1);
    const int b = idx >> 15;

    const float M1 = g_M1[idx];
    const float M2 = g_M2[idx];

    const float lgt = logits[b * QQ + q];
    const float cls = fmaxf(-lgt, 0.f) + log1pf(__expf(-fabsf(lgt)));   // softplus(-logit)
    const float nnz = fmaxf(g_nnz[b], 1.f);
    const float maskc = (M1 + g_negsum[b * QQ + q]) / nnz;
    const float dice  = 1.f - (2.f * M2 + 1.f) / (g_psum[b * QQ + q] + g_segsum[b * EE + e] + 1.f);

    const float px = ppos[(b * QQ + q) * 2 + 0], py = ppos[(b * QQ + q) * 2 + 1];
    const float tx = tpos[(b * EE + e) * 2 + 0], ty = tpos[(b * EE + e) * 2 + 1];
    const float d0 = px - tx, d1 = py - ty;
    const float a0 = fabsf(d0), a1 = fabsf(d1);
    const float h0 = (a0 < 1.f) ? 0.5f * d0 * d0 : a0 - 0.5f;
    const float h1 = (a1 < 1.f) ? 0.5f * d1 * d1 : a1 - 0.5f;
    const float hub = 0.5f * (h0 + h1);

    const float sx = imsz[b * 2 + 0], sy = imsz[b * 2 + 1];
    const float L00 = chol[(b * QQ + q) * 4 + 0];
    const float L10 = chol[(b * QQ + q) * 4 + 2];
    const float L11 = chol[(b * QQ + q) * 4 + 3];
    const float D0 = (tx - px) * sx, D1 = (ty - py) * sy;
    const float z0 = D0 / L00;
    const float z1 = (D1 - L10 * z0) / L11;
    const float nll = 0.5f * (z0 * z0 + z1 * z1) + 1.837877066409345f + logf(L00) + logf(L11);
    const float lik = 1.f - __expf(-nll);

    out[idx] = 2.f * cls + 5.f * maskc + 5.f * dice + hub + 0.5f * nll + 0.5f * lik;
}

// ---------------- launch -----------------------------------------------------
extern "C" void kernel_launch(void* const* d_in, const int* in_sizes, int n_in,
                              void* d_out, int out_size)
{
    const float* pred_logits = (const float*)d_in[0];
    const float* mlv         = (const float*)d_in[1];
    const void*  mm          = d_in[2];
    const float* seg         = (const float*)d_in[3];
    const float* ppos        = (const float*)d_in[4];
    const float* chol        = (const float*)d_in[5];
    const float* tpos        = (const float*)d_in[6];
    const float* imsz        = (const float*)d_in[7];
    float* out = (float*)d_out;

    int nwords = in_sizes[2] / 4;
    if (nwords > 65536) nwords = 65536;

    k_detect<<<1, 1024>>>((const unsigned int*)mm, nwords);
    k_init<<<128, 256>>>();

    dim3 gA(PCHUNKS_A, BB);
    k_passA<<<gA, 256>>>(mlv, mm, seg);

    const int shB = 2 * EQW * QS * (int)sizeof(float);
    cudaFuncSetAttribute(k_passB, cudaFuncAttributeMaxDynamicSharedMemorySize, shB);
    dim3 gB(EQ, BB, PCB);
    k_passB<<<gB, 256, shB>>>();

    k_final<<<(BB * QQ * EE + 255) / 256, 256>>>(pred_logits, ppos, chol, tpos, imsz, out);
}

// round 3
// speedup vs baseline: 3.7986x; 1.3963x over previous
#include <cuda_runtime.h>
#include <cuda_fp16.h>
#include <math.h>

#define BB 8
#define PP 16384
#define QQ 256
#define EE 128
#define PCH 128
#define PIXM (PP/PCH)        // 128 pixels per block

// ---------------- scratch (static device globals; no allocation) -------------
__device__ int     g_mask_dtype;          // 0=bool/u8, 1=f32, 2=i32
__device__ float   g_negsum[BB*QQ];
__device__ float   g_psum  [BB*QQ];
__device__ float   g_segsum[BB*EE];
__device__ float   g_nnz   [BB];
__device__ __half2 g_M[BB*EE*QQ];         // packed (M1, M2), layout [b][e][q], 1 MB

// ---------------- dtype detection for mask_mask ------------------------------
__global__ void k_detect(const unsigned int* __restrict__ w, int nwords) {
    __shared__ int sF, sB;
    if (threadIdx.x == 0) { sF = 0; sB = 0; }
    __syncthreads();
    int f = 0, bl = 0;
    for (int i = threadIdx.x; i < nwords; i += blockDim.x) {
        unsigned v = __ldg(w + i);
        if (v == 0x3F800000u) f = 1;
        else if (v & 0xFFFFFF00u) bl = 1;
    }
    if (f)  atomicOr(&sF, 1);
    if (bl) atomicOr(&sB, 1);
    __syncthreads();
    if (threadIdx.x == 0) g_mask_dtype = sF ? 1 : (sB ? 0 : 2);
}

// ---------------- zero accumulators ------------------------------------------
__global__ void k_init() {
    const int t = blockIdx.x * blockDim.x + threadIdx.x;   // 64*256 = 16384 threads
    uint4 z = make_uint4(0u, 0u, 0u, 0u);
    uint4* m = reinterpret_cast<uint4*>(g_M);              // 65536 uint4
    #pragma unroll
    for (int r = 0; r < 4; r++) m[t + r * 16384] = z;
    if (t < BB*QQ) { g_negsum[t] = 0.f; g_psum[t] = 0.f; }
    if (t < BB*EE) g_segsum[t] = 0.f;
    if (t < BB) g_nnz[t] = 0.f;
}

// ---------------- fused main pass --------------------------------------------
__global__ void __launch_bounds__(256) k_main(
    const float* __restrict__ mlv, const void* __restrict__ maskp,
    const float* __restrict__ seg)
{
    const int b = blockIdx.y, pc = blockIdx.x;
    const int lane = threadIdx.x & 31, w = threadIdx.x >> 5;
    const int mdt = g_mask_dtype;
    const int q0 = lane * 8;

    float negacc[8], psacc[8], segacc[4];
    #pragma unroll
    for (int j = 0; j < 8; j++) { negacc[j] = 0.f; psacc[j] = 0.f; }
    #pragma unroll
    for (int j = 0; j < 4; j++) segacc[j] = 0.f;
    float nnzacc = 0.f;

    __half2* Mb = g_M + (size_t)b * EE * QQ;

    for (int pi = w; pi < PIXM; pi += 8) {
        const size_t pix  = (size_t)b * PP + pc * PIXM + pi;
        const size_t rowQ = pix * QQ;

        // --- 8 logits (vectorized) ---
        const float4* xr = reinterpret_cast<const float4*>(mlv + rowQ);
        float4 xa = xr[lane*2], xb = xr[lane*2 + 1];
        float x[8] = {xa.x, xa.y, xa.z, xa.w, xb.x, xb.y, xb.z, xb.w};

        // --- 8 mask flags per detected dtype ---
        unsigned mbits = 0;
        if (mdt == 0) {
            const unsigned char* mv = (const unsigned char*)maskp + rowQ;
            uint2 u = *reinterpret_cast<const uint2*>(mv + (size_t)lane * 8);
            #pragma unroll
            for (int j = 0; j < 4; j++) {
                if ((u.x >> (8*j)) & 0xffu) mbits |= 1u << j;
                if ((u.y >> (8*j)) & 0xffu) mbits |= 1u << (4 + j);
            }
        } else if (mdt == 1) {
            const float4* mv = reinterpret_cast<const float4*>((const float*)maskp + rowQ);
            float4 a = mv[lane*2], c = mv[lane*2 + 1];
            float mm[8] = {a.x, a.y, a.z, a.w, c.x, c.y, c.z, c.w};
            #pragma unroll
            for (int j = 0; j < 8; j++) if (mm[j] != 0.f) mbits |= 1u << j;
        } else {
            const int4* mv = reinterpret_cast<const int4*>((const int*)maskp + rowQ);
            int4 a = mv[lane*2], c = mv[lane*2 + 1];
            int mm[8] = {a.x, a.y, a.z, a.w, c.x, c.y, c.z, c.w};
            #pragma unroll
            for (int j = 0; j < 8; j++) if (mm[j] != 0) mbits |= 1u << j;
        }

        // --- masked row max over Q ---
        float mx = -1e30f;
        #pragma unroll
        for (int j = 0; j < 8; j++) if ((mbits >> j) & 1) mx = fmaxf(mx, x[j]);
        #pragma unroll
        for (int o = 16; o; o >>= 1) mx = fmaxf(mx, __shfl_xor_sync(0xffffffffu, mx, o));

        // --- exp + sum ---
        float ez[8]; float s = 0.f;
        #pragma unroll
        for (int j = 0; j < 8; j++) {
            ez[j] = ((mbits >> j) & 1) ? __expf(x[j] - mx) : 0.f;
            s += ez[j];
        }
        #pragma unroll
        for (int o = 16; o; o >>= 1) s += __shfl_xor_sync(0xffffffffu, s, o);
        const float inv = (s > 0.f) ? (1.f / s) : 0.f;

        // --- per-lane q-slot prep (nibble-packed list of set j's) ---
        __half a1h[8]; float ppf[8];
        unsigned jlist = 0; int jn = 0;
        #pragma unroll
        for (int j = 0; j < 8; j++) {
            ppf[j] = ez[j] * inv;
            if ((mbits >> j) & 1) {
                a1h[j] = __float2half(-x[j]);
                float xx = x[j];
                negacc[j] += fmaxf(xx, 0.f) + log1pf(__expf(-fabsf(xx)));  // softplus(x)
                psacc[j]  += ppf[j];
                jlist |= (unsigned)j << (4 * jn); jn++;
            }
        }

        // --- segmap row (E=128, 4 per lane) ---
        const float4 sv4 = reinterpret_cast<const float4*>(seg + pix * EE)[lane];
        float sv[4] = {sv4.x, sv4.y, sv4.z, sv4.w};
        #pragma unroll
        for (int j = 0; j < 4; j++) {
            segacc[j] += sv[j];                 // zeros where unoccupied
            if (sv[j] > 0.f) nnzacc += 1.f;
        }

        // --- fused sparse outer product: one half2 RED per (q,e) pair ---
        #pragma unroll
        for (int j4 = 0; j4 < 4; j4++) {
            unsigned bal = __ballot_sync(0xffffffffu, sv[j4] > 0.f);
            while (bal) {
                const int o = __ffs(bal) - 1; bal &= bal - 1;
                const float svv = __shfl_sync(0xffffffffu, sv[j4], o);
                const int e = o * 4 + j4;
                __half2* Me = Mb + e * QQ + q0;
                unsigned jl = jlist;
                for (int k = 0; k < jn; k++) {
                    const int j = jl & 15; jl >>= 4;
                    __half2 v = __halves2half2(a1h[j], __float2half(ppf[j] * svv));
                    atomicAdd(Me + j, v);
                }
            }
        }
    }

    // --- flush register accumulators (global RED) ---
    #pragma unroll
    for (int j = 0; j < 8; j++) {
        if (negacc[j] != 0.f) atomicAdd(&g_negsum[b*QQ + q0 + j], negacc[j]);
        if (psacc[j]  != 0.f) atomicAdd(&g_psum  [b*QQ + q0 + j], psacc[j]);
    }
    #pragma unroll
    for (int j = 0; j < 4; j++)
        if (segacc[j] != 0.f) atomicAdd(&g_segsum[b*EE + lane*4 + j], segacc[j]);
    #pragma unroll
    for (int o = 16; o; o >>= 1) nnzacc += __shfl_xor_sync(0xffffffffu, nnzacc, o);
    if (lane == 0 && nnzacc != 0.f) atomicAdd(&g_nnz[b], nnzacc);
}

// ---------------- final: per-(b,e,q) costs -----------------------------------
__global__ void __launch_bounds__(256) k_final(
    const float* __restrict__ logits, const float* __restrict__ ppos,
    const float* __restrict__ chol,   const float* __restrict__ tpos,
    const float* __restrict__ imsz,   float* __restrict__ out)
{
    const int idx = blockIdx.x * 256 + threadIdx.x;   // idx = (b*EE+e)*QQ + q
    if (idx >= BB * QQ * EE) return;
    const int q = idx & (QQ - 1);
    const int e = (idx >> 8) & (EE - 1);
    const int b = idx >> 15;

    const __half2 m = g_M[idx];
    const float M1 = __low2float(m);
    const float M2 = __high2float(m);

    const float lgt = logits[b * QQ + q];
    const float cls = fmaxf(-lgt, 0.f) + log1pf(__expf(-fabsf(lgt)));   // softplus(-logit)
    const float nnz = fmaxf(g_nnz[b], 1.f);
    const float maskc = (M1 + g_negsum[b * QQ + q]) / nnz;
    const float dice  = 1.f - (2.f * M2 + 1.f) / (g_psum[b * QQ + q] + g_segsum[b * EE + e] + 1.f);

    const float px = ppos[(b * QQ + q) * 2 + 0], py = ppos[(b * QQ + q) * 2 + 1];
    const float tx = tpos[(b * EE + e) * 2 + 0], ty = tpos[(b * EE + e) * 2 + 1];
    const float d0 = px - tx, d1 = py - ty;
    const float a0 = fabsf(d0), a1 = fabsf(d1);
    const float h0 = (a0 < 1.f) ? 0.5f * d0 * d0 : a0 - 0.5f;
    const float h1 = (a1 < 1.f) ? 0.5f * d1 * d1 : a1 - 0.5f;
    const float hub = 0.5f * (h0 + h1);

    const float sx = imsz[b * 2 + 0], sy = imsz[b * 2 + 1];
    const float L00 = chol[(b * QQ + q) * 4 + 0];
    const float L10 = chol[(b * QQ + q) * 4 + 2];
    const float L11 = chol[(b * QQ + q) * 4 + 3];
    const float D0 = (tx - px) * sx, D1 = (ty - py) * sy;
    const float z0 = D0 / L00;
    const float z1 = (D1 - L10 * z0) / L11;
    const float nll = 0.5f * (z0 * z0 + z1 * z1) + 1.837877066409345f + logf(L00) + logf(L11);
    const float lik = 1.f - __expf(-nll);

    out[(b * QQ + q) * EE + e] =
        2.f * cls + 5.f * maskc + 5.f * dice + hub + 0.5f * nll + 0.5f * lik;
}

// ---------------- launch -----------------------------------------------------
extern "C" void kernel_launch(void* const* d_in, const int* in_sizes, int n_in,
                              void* d_out, int out_size)
{
    const float* pred_logits = (const float*)d_in[0];
    const float* mlv         = (const float*)d_in[1];
    const void*  mm          = d_in[2];
    const float* seg         = (const float*)d_in[3];
    const float* ppos        = (const float*)d_in[4];
    const float* chol        = (const float*)d_in[5];
    const float* tpos        = (const float*)d_in[6];
    const float* imsz        = (const float*)d_in[7];
    float* out = (float*)d_out;

    int nwords = in_sizes[2] / 4;
    if (nwords > 65536) nwords = 65536;

    k_detect<<<1, 1024>>>((const unsigned int*)mm, nwords);
    k_init<<<64, 256>>>();

    dim3 gM(PCH, BB);
    k_main<<<gM, 256>>>(mlv, mm, seg);

    k_final<<<(BB * QQ * EE + 255) / 256, 256>>>(pred_logits, ppos, chol, tpos, imsz, out);
}